// round 12
// baseline (speedup 1.0000x reference)
#include <cuda_runtime.h>

#define FULL_MASK 0xFFFFFFFFu
static constexpr int HID = 32;
static constexpr int TT = 1024;
// block = 2 warps; each warp = 2 cells (16 lanes per cell, 2 hids per lane)
static constexpr int CELLS_PER_CTA = 4;

__device__ __forceinline__ unsigned long long pack2(float lo, float hi) {
    unsigned long long r;
    asm("mov.b64 %0, {%1, %2};" : "=l"(r) : "f"(lo), "f"(hi));
    return r;
}
__device__ __forceinline__ void unpack2(unsigned long long v, float& lo, float& hi) {
    asm("mov.b64 {%0, %1}, %2;" : "=f"(lo), "=f"(hi) : "l"(v));
}
__device__ __forceinline__ unsigned long long fma2(unsigned long long a,
                                                   unsigned long long b,
                                                   unsigned long long c) {
    unsigned long long d;
    asm("fma.rn.f32x2 %0, %1, %2, %3;" : "=l"(d) : "l"(a), "l"(b), "l"(c));
    return d;
}
__device__ __forceinline__ float tanh_approx(float x) {
    float r; asm("tanh.approx.f32 %0, %1;" : "=f"(r) : "f"(x)); return r;
}

// 2 cells per warp: half = lane>>4 selects the cell, m = lane&15; the lane
// computes hidden units m and m+16 of its cell (8 dot products of length 32
// = 128 fma2/warp-step = 64/cell, same arithmetic as before).
// i,f weight rows: registers (64 regs, prescaled 0.5 for sigmoid-via-tanh).
// g,o weight rows: CTA smem, layout [kp2][row][4 floats] so the 16 distinct
// row addresses of one LDS.128 are contiguous (2 wavefronts, no conflicts).
// h: per-warp smem ping-pong, cell buffers offset 48 floats (bank-disjoint
// STS halves); LDS.128 of h is a half-warp broadcast (1 wf).
// 14 warps/SM resident => ALL 2048 warps in ONE wave: no tail.
__global__ void __launch_bounds__(64, 7)
lstm_kernel(const float* __restrict__ x,
            const float* __restrict__ W_ih,
            const float* __restrict__ W_hh,
            const float* __restrict__ b_ih,
            const float* __restrict__ b_hh,
            const float* __restrict__ fc_W,
            const float* __restrict__ fc_b,
            float* __restrict__ out, int B)
{
    // g,o weights: 64 rows x 32 k = 2048 floats = 8KB, [kp2][row][4]
    __shared__ __align__(16) float go[2048];
    // h ping-pong: [warpInBlock][pp][96] ; cellA at +0, cellB at +48 floats
    __shared__ __align__(16) float hb[2][2][96];

    const int tid  = threadIdx.x;
    const int wib  = tid >> 5;          // warp in block: 0/1
    const int lane = tid & 31;
    const int half = lane >> 4;         // 0 = cell A, 1 = cell B
    const int m    = lane & 15;         // first owned hidden unit
    const int m2   = m + 16;            // second owned hidden unit

    // fill g,o smem (gate order i,f,g,o: g = rows 64..95, o = rows 96..127)
    for (int e = tid; e < 2048; e += 64) {
        const int kp2 = e >> 8;         // 0..7
        const int rem = e & 255;
        const int row = rem >> 2;       // 0..63 (0-31 g, 32-63 o)
        const int j   = rem & 3;
        const int k   = kp2 * 4 + j;
        const int src = (row < 32) ? (64 + row) : (96 + (row - 32));
        const float sc = (row < 32) ? 1.0f : 0.5f;   // g: tanh, o: sigmoid/2
        go[e] = sc * W_hh[src * HID + k];
    }
    __syncthreads();

    const int cell0 = blockIdx.x * CELLS_PER_CTA + wib * 2;
    const int cell  = min(cell0 + half, B - 1);

    // register weights: rows (i,m),(f,m),(i,m2),(f,m2), prescaled 0.5
    unsigned long long Wr[4][HID / 2];
    {
        const int rows[4] = { 0 * HID + m, 1 * HID + m, 0 * HID + m2, 1 * HID + m2 };
        #pragma unroll
        for (int r = 0; r < 4; ++r) {
            const float* wrow = W_hh + rows[r] * HID;
            #pragma unroll
            for (int kp = 0; kp < HID / 2; ++kp)
                Wr[r][kp] = pack2(0.5f * wrow[2 * kp], 0.5f * wrow[2 * kp + 1]);
        }
    }
    // per-lane gate bases for its 8 rows: (i,f,g,o) x (m, m2)
    float wih[8], bias[8];
    {
        const int gs[4] = { 0, 1, 2, 3 };
        #pragma unroll
        for (int g = 0; g < 4; ++g) {
            const float sc = (g == 2) ? 1.0f : 0.5f;
            wih[g]      = sc * W_ih[gs[g] * HID + m];
            wih[4 + g]  = sc * W_ih[gs[g] * HID + m2];
            bias[g]     = sc * (b_ih[gs[g] * HID + m]  + b_hh[gs[g] * HID + m]);
            bias[4 + g] = sc * (b_ih[gs[g] * HID + m2] + b_hh[gs[g] * HID + m2]);
        }
    }

    float h_m = 0.0f, h_m2 = 0.0f, c_m = 0.0f, c_m2 = 0.0f;
    const float* myx = x + (size_t)cell * TT;

    const ulonglong2* gov = reinterpret_cast<const ulonglong2*>(go);
    const int hbase = half * 48;        // float offset of my cell's h buffer

    for (int t16 = 0; t16 < TT; t16 += 16) {
        // halfA lanes hold xA[t16+m], halfB lanes hold xB[t16+m]
        const float xbuf = myx[t16 + m];
        #pragma unroll 1
        for (int s = 0; s < 16; ++s) {
            // publish h for this step (ping-pong), then read whole h back
            float* buf = hb[wib][s & 1];
            buf[hbase + m]  = h_m;
            buf[hbase + m2] = h_m2;

            const float xv = __shfl_sync(FULL_MASK, xbuf, (lane & 16) | s);

            // acc init = (x*wih + bias, 0) for all 8 rows
            unsigned long long a_im  = pack2(fmaf(xv, wih[0], bias[0]), 0.0f);
            unsigned long long a_fm  = pack2(fmaf(xv, wih[1], bias[1]), 0.0f);
            unsigned long long a_gm  = pack2(fmaf(xv, wih[2], bias[2]), 0.0f);
            unsigned long long a_om  = pack2(fmaf(xv, wih[3], bias[3]), 0.0f);
            unsigned long long a_im2 = pack2(fmaf(xv, wih[4], bias[4]), 0.0f);
            unsigned long long a_fm2 = pack2(fmaf(xv, wih[5], bias[5]), 0.0f);
            unsigned long long a_gm2 = pack2(fmaf(xv, wih[6], bias[6]), 0.0f);
            unsigned long long a_om2 = pack2(fmaf(xv, wih[7], bias[7]), 0.0f);

            const ulonglong2* hp =
                reinterpret_cast<const ulonglong2*>(buf + hbase);
            #pragma unroll
            for (int kp2 = 0; kp2 < 8; ++kp2) {
                const ulonglong2 h4 = hp[kp2];              // 2 h-pairs, bcast
                const ulonglong2 wgm  = gov[kp2 * 64 + m];        // g,m
                const ulonglong2 wgm2 = gov[kp2 * 64 + m2];       // g,m2
                const ulonglong2 wom  = gov[kp2 * 64 + 32 + m];   // o,m
                const ulonglong2 wom2 = gov[kp2 * 64 + 48 + m];   // o,m2
                a_im  = fma2(Wr[0][2 * kp2],     h4.x, a_im);
                a_fm  = fma2(Wr[1][2 * kp2],     h4.x, a_fm);
                a_im2 = fma2(Wr[2][2 * kp2],     h4.x, a_im2);
                a_fm2 = fma2(Wr[3][2 * kp2],     h4.x, a_fm2);
                a_gm  = fma2(wgm.x,  h4.x, a_gm);
                a_gm2 = fma2(wgm2.x, h4.x, a_gm2);
                a_om  = fma2(wom.x,  h4.x, a_om);
                a_om2 = fma2(wom2.x, h4.x, a_om2);
                a_im  = fma2(Wr[0][2 * kp2 + 1], h4.y, a_im);
                a_fm  = fma2(Wr[1][2 * kp2 + 1], h4.y, a_fm);
                a_im2 = fma2(Wr[2][2 * kp2 + 1], h4.y, a_im2);
                a_fm2 = fma2(Wr[3][2 * kp2 + 1], h4.y, a_fm2);
                a_gm  = fma2(wgm.y,  h4.y, a_gm);
                a_gm2 = fma2(wgm2.y, h4.y, a_gm2);
                a_om  = fma2(wom.y,  h4.y, a_om);
                a_om2 = fma2(wom2.y, h4.y, a_om2);
            }

            float lo, hi;
            unpack2(a_im,  lo, hi); const float ti  = tanh_approx(lo + hi);
            unpack2(a_fm,  lo, hi); const float tf  = tanh_approx(lo + hi);
            unpack2(a_gm,  lo, hi); const float gg  = tanh_approx(lo + hi);
            unpack2(a_om,  lo, hi); const float to  = tanh_approx(lo + hi);
            unpack2(a_im2, lo, hi); const float ti2 = tanh_approx(lo + hi);
            unpack2(a_fm2, lo, hi); const float tf2 = tanh_approx(lo + hi);
            unpack2(a_gm2, lo, hi); const float gg2 = tanh_approx(lo + hi);
            unpack2(a_om2, lo, hi); const float to2 = tanh_approx(lo + hi);

            const float ig  = fmaf(0.5f, ti,  0.5f);
            const float fg  = fmaf(0.5f, tf,  0.5f);
            const float og  = fmaf(0.5f, to,  0.5f);
            const float ig2 = fmaf(0.5f, ti2, 0.5f);
            const float fg2 = fmaf(0.5f, tf2, 0.5f);
            const float og2 = fmaf(0.5f, to2, 0.5f);

            c_m  = fmaf(fg,  c_m,  ig  * gg);
            c_m2 = fmaf(fg2, c_m2, ig2 * gg2);
            h_m  = og  * tanh_approx(c_m);
            h_m2 = og2 * tanh_approx(c_m2);
        }
    }

    // out[cell] = h . fc_W + fc_b : reduce within the 16-lane half
    float v = h_m * fc_W[m] + h_m2 * fc_W[m2];
    v += __shfl_xor_sync(FULL_MASK, v, 8);
    v += __shfl_xor_sync(FULL_MASK, v, 4);
    v += __shfl_xor_sync(FULL_MASK, v, 2);
    v += __shfl_xor_sync(FULL_MASK, v, 1);
    if (m == 0 && cell0 + half < B)
        out[cell] = v + fc_b[0];
}

extern "C" void kernel_launch(void* const* d_in, const int* in_sizes, int n_in,
                              void* d_out, int out_size) {
    const float* x    = (const float*)d_in[0];
    const float* W_ih = (const float*)d_in[1];
    const float* W_hh = (const float*)d_in[2];
    const float* b_ih = (const float*)d_in[3];
    const float* b_hh = (const float*)d_in[4];
    const float* fc_W = (const float*)d_in[5];
    const float* fc_b = (const float*)d_in[6];
    float* out = (float*)d_out;

    const int B = in_sizes[0] / TT;           // x is B*T*1 elements
    const int ctas = (B + CELLS_PER_CTA - 1) / CELLS_PER_CTA;
    lstm_kernel<<<ctas, 64>>>(x, W_ih, W_hh, b_ih, b_hh, fc_W, fc_b, out, B);
}

// round 13
// speedup vs baseline: 2.2708x; 2.2708x over previous
#include <cuda_runtime.h>

#define FULL_MASK 0xFFFFFFFFu
static constexpr int HID = 32;
static constexpr int TT = 1024;

// ---- packed f32x2 helpers (sm_103a; ptxas never auto-fuses these) ----
__device__ __forceinline__ unsigned long long pack2(float lo, float hi) {
    unsigned long long r;
    asm("mov.b64 %0, {%1, %2};" : "=l"(r) : "f"(lo), "f"(hi));
    return r;
}
__device__ __forceinline__ void unpack2(unsigned long long v, float& lo, float& hi) {
    asm("mov.b64 {%0, %1}, %2;" : "=f"(lo), "=f"(hi) : "l"(v));
}
__device__ __forceinline__ unsigned long long fma2(unsigned long long a,
                                                   unsigned long long b,
                                                   unsigned long long c) {
    unsigned long long d;
    asm("fma.rn.f32x2 %0, %1, %2, %3;" : "=l"(d) : "l"(a), "l"(b), "l"(c));
    return d;
}
// single-MUFU tanh (MUFU.TANH; measured 8.9e-7 end-to-end here)
__device__ __forceinline__ float tanh_approx(float x) {
    float r; asm("tanh.approx.f32 %0, %1;" : "=f"(r) : "f"(x)); return r;
}

// One warp per cell = one CTA (32 threads). lane j owns hidden unit j.
// k-packed weights in 128 registers; sigmoid via 0.5+0.5*tanh(x/2) with the
// /2 prescaled into the i,f,o rows. h broadcast via per-CTA smem ping-pong.
//
// ROUND-13:
//  (1) x double-buffer: the next 32-step chunk's LDG is issued a full chunk
//      (~5000 cyc) before use — removes a ~600-cyc cold LDG stall that hit
//      every warp every 32 steps (~19 cyc/step, half the steady-state gap).
//  (2) 32-thread CTAs (12/SM): wave-3 leftovers pack at warp granularity
//      instead of 4-warp granularity; CLC backfills finished slots.
__global__ void __launch_bounds__(32, 12)
lstm_kernel(const float* __restrict__ x,
            const float* __restrict__ W_ih,
            const float* __restrict__ W_hh,
            const float* __restrict__ b_ih,
            const float* __restrict__ b_hh,
            const float* __restrict__ fc_W,
            const float* __restrict__ fc_b,
            float* __restrict__ out, int B)
{
    __shared__ __align__(16) float hbuf[2][HID];
    const int lane = threadIdx.x & 31;
    const int b = blockIdx.x;

    // Gate order (PyTorch): rows [0:32)=i, [32:64)=f, [64:96)=g, [96:128)=o
    // Prescale i,f,o rows by 0.5 (sigmoid-via-tanh); g row unscaled.
    const float gscale[4] = { 0.5f, 0.5f, 1.0f, 0.5f };
    unsigned long long Wg[4][HID / 2];
    #pragma unroll
    for (int g = 0; g < 4; ++g) {
        const float* wrow = W_hh + (g * HID + lane) * HID;
        const float sc = gscale[g];
        #pragma unroll
        for (int k2 = 0; k2 < HID / 2; ++k2)
            Wg[g][k2] = pack2(sc * wrow[2 * k2], sc * wrow[2 * k2 + 1]);
    }
    const float wih_i = 0.5f * W_ih[0 * HID + lane];
    const float wih_f = 0.5f * W_ih[1 * HID + lane];
    const float wih_g =        W_ih[2 * HID + lane];
    const float wih_o = 0.5f * W_ih[3 * HID + lane];
    const float bias_i = 0.5f * (b_ih[0 * HID + lane] + b_hh[0 * HID + lane]);
    const float bias_f = 0.5f * (b_ih[1 * HID + lane] + b_hh[1 * HID + lane]);
    const float bias_g =        (b_ih[2 * HID + lane] + b_hh[2 * HID + lane]);
    const float bias_o = 0.5f * (b_ih[3 * HID + lane] + b_hh[3 * HID + lane]);

    float h = 0.0f, c = 0.0f;
    const float* xrow = x + (size_t)b * TT;   // x is [B, T, 1]

    // prime the x double-buffer with chunk 0
    float xbuf = xrow[lane];

    for (int t0 = 0; t0 < TT; t0 += 32) {
        // prefetch NEXT chunk now; consumed 32 steps from now (fully hidden)
        const int nidx = min(t0 + 32 + lane, TT - 1);
        const float xnext = xrow[nidx];

        #pragma unroll 1
        for (int s = 0; s < 32; ++s) {
            // publish h first — STS commit hides under shfl + base fmas
            float* buf = hbuf[s & 1];
            buf[lane] = h;

            const float xv = __shfl_sync(FULL_MASK, xbuf, s);
            unsigned long long ai = pack2(fmaf(xv, wih_i, bias_i), 0.0f);
            unsigned long long af = pack2(fmaf(xv, wih_f, bias_f), 0.0f);
            unsigned long long ag = pack2(fmaf(xv, wih_g, bias_g), 0.0f);
            unsigned long long ao = pack2(fmaf(xv, wih_o, bias_o), 0.0f);

            const ulonglong2* hp = reinterpret_cast<const ulonglong2*>(buf);
            #pragma unroll
            for (int k4 = 0; k4 < HID / 4; ++k4) {
                const ulonglong2 hk = hp[k4];   // LDS.128 broadcast: 2 h-pairs
                ai = fma2(Wg[0][2 * k4], hk.x, ai);
                af = fma2(Wg[1][2 * k4], hk.x, af);
                ag = fma2(Wg[2][2 * k4], hk.x, ag);
                ao = fma2(Wg[3][2 * k4], hk.x, ao);
                ai = fma2(Wg[0][2 * k4 + 1], hk.y, ai);
                af = fma2(Wg[1][2 * k4 + 1], hk.y, af);
                ag = fma2(Wg[2][2 * k4 + 1], hk.y, ag);
                ao = fma2(Wg[3][2 * k4 + 1], hk.y, ao);
            }

            float lo, hi;
            unpack2(ai, lo, hi);  const float ti = tanh_approx(lo + hi);
            unpack2(af, lo, hi);  const float tf = tanh_approx(lo + hi);
            unpack2(ag, lo, hi);  const float gg = tanh_approx(lo + hi);
            unpack2(ao, lo, hi);  const float to = tanh_approx(lo + hi);

            const float ig = fmaf(0.5f, ti, 0.5f);
            const float fg = fmaf(0.5f, tf, 0.5f);
            const float og = fmaf(0.5f, to, 0.5f);

            c = fmaf(fg, c, ig * gg);
            h = og * tanh_approx(c);
        }
        xbuf = xnext;
    }

    // out[b] = h . fc_W + fc_b  (warp reduce)
    float v = h * fc_W[lane];
    #pragma unroll
    for (int off = 16; off; off >>= 1)
        v += __shfl_xor_sync(FULL_MASK, v, off);
    if (lane == 0) out[b] = v + fc_b[0];
}

extern "C" void kernel_launch(void* const* d_in, const int* in_sizes, int n_in,
                              void* d_out, int out_size) {
    const float* x    = (const float*)d_in[0];
    const float* W_ih = (const float*)d_in[1];
    const float* W_hh = (const float*)d_in[2];
    const float* b_ih = (const float*)d_in[3];
    const float* b_hh = (const float*)d_in[4];
    const float* fc_W = (const float*)d_in[5];
    const float* fc_b = (const float*)d_in[6];
    float* out = (float*)d_out;

    const int B = in_sizes[0] / TT;           // x is B*T*1 elements
    lstm_kernel<<<B, 32>>>(x, W_ih, W_hh, b_ih, b_hh, fc_W, fc_b, out, B);
}